// round 16
// baseline (speedup 1.0000x reference)
#include <cuda_runtime.h>
#include <cstdint>

#define BB 4
#define HH 16
#define SSEQ 2048
#define DDIM 64
#define NELEM ((size_t)BB * HH * SSEQ * DDIM)     // 8388608
#define OUT_O_ELEMS NELEM

#define KC 64
#define NCH (SSEQ / KC)       // 32
#define STK 68                // K smem stride (floats)
#define STV 72                // V smem stride (floats)

#define SM1_BYTES (2 * KC * STK * 4)                       // 34816
#define SM2_BYTES ((2 * KC * STK + 2 * KC * STV) * 4)      // 71680 -> 3 CTAs

__device__ int g_maskFlag = 0;
__device__ float g_li[(size_t)BB * HH * SSEQ];   // 1/rowsum
__device__ float g_qt[NELEM];                    // tf32(q/8)
__device__ float g_kt[NELEM];                    // tf32(k)
__device__ float g_vt[NELEM];                    // tf32(v)

__device__ __forceinline__ uint32_t f2tf32(float x) {
    uint32_t r;
    asm("cvt.rna.tf32.f32 %0, %1;" : "=r"(r) : "f"(x));
    return r;
}
__device__ __forceinline__ float tf(float x) { return __uint_as_float(f2tf32(x)); }

__device__ __forceinline__ uint32_t smaddr(const void* p) {
    uint32_t a;
    asm("{ .reg .u64 t; cvta.to.shared.u64 t, %1; cvt.u32.u64 %0, t; }" : "=r"(a) : "l"(p));
    return a;
}
#define CPA16(d, s)   asm volatile("cp.async.cg.shared.global [%0], [%1], 16;" :: "r"(d), "l"(s))
#define CPA_COMMIT()  asm volatile("cp.async.commit_group;" ::: "memory")
#define CPA_WAIT0()   asm volatile("cp.async.wait_group 0;" ::: "memory")

__device__ __forceinline__ void mma_tf32(float* c,
                                         uint32_t a0, uint32_t a1, uint32_t a2, uint32_t a3,
                                         uint32_t b0, uint32_t b1) {
    asm volatile(
        "mma.sync.aligned.m16n8k8.row.col.f32.tf32.tf32.f32 "
        "{%0,%1,%2,%3}, {%4,%5,%6,%7}, {%8,%9}, {%0,%1,%2,%3};"
        : "+f"(c[0]), "+f"(c[1]), "+f"(c[2]), "+f"(c[3])
        : "r"(a0), "r"(a1), "r"(a2), "r"(a3), "r"(b0), "r"(b1));
}

__global__ void mask_check(const float* __restrict__ mask, size_t n) {
    size_t i = (size_t)blockIdx.x * blockDim.x + threadIdx.x;
    uint32_t any = 0;
    const size_t stride = (size_t)gridDim.x * blockDim.x;
    for (; i < n; i += stride) any |= __float_as_uint(mask[i]);
    if (__any_sync(0xffffffffu, any != 0u) && (threadIdx.x & 31) == 0)
        atomicOr(&g_maskFlag, 1);
}

// ---- prep: tf32-preconvert q (pre-scaled), k, v ----
__global__ void prep(const float* __restrict__ q, const float* __restrict__ k,
                     const float* __restrict__ v) {
    const size_t n4 = NELEM / 4;
    const size_t stride = (size_t)gridDim.x * blockDim.x;
    for (size_t i = (size_t)blockIdx.x * blockDim.x + threadIdx.x; i < n4; i += stride) {
        float4 a = ((const float4*)q)[i];
        ((float4*)g_qt)[i] = make_float4(tf(a.x * 0.125f), tf(a.y * 0.125f),
                                         tf(a.z * 0.125f), tf(a.w * 0.125f));
        float4 b = ((const float4*)k)[i];
        ((float4*)g_kt)[i] = make_float4(tf(b.x), tf(b.y), tf(b.z), tf(b.w));
        float4 c = ((const float4*)v)[i];
        ((float4*)g_vt)[i] = make_float4(tf(c.x), tf(c.y), tf(c.z), tf(c.w));
    }
}

// ============================================================
// K1: g_li = 1 / sum_j exp(s_ij). 128 q-rows/CTA, 4 warps, 16 warps/SM.
// K chunks streamed via cp.async double buffer; no stores in loop.
// ============================================================
__global__ __launch_bounds__(128, 4)
void qk_li(const float* __restrict__ mask) {
    extern __shared__ float sm[];
    const int tid = threadIdx.x;
    const int warp = tid >> 5, lane = tid & 31;
    const int grp = lane >> 2, tid4 = lane & 3;
    const int mt = blockIdx.x, bh = blockIdx.y;
    const int q0 = mt * 128;
    const int m0 = warp * 32;
    const size_t base = (size_t)bh * SSEQ * DDIM;
    const int mflag = *(volatile int*)&g_maskFlag;
    const uint32_t sb = smaddr(sm);

    const float* qt = g_qt + base + (size_t)q0 * DDIM;
    const float* kt = g_kt + base;

    // ---- stage Q (tf32, pre-scaled) via cp.async over both K buffers ----
    #pragma unroll
    for (int i = 0; i < 16; i++) {
        int idx = tid + i * 128;
        CPA16(sb + (((idx >> 4) * STK + (idx & 15) * 4) << 2), qt + idx * 4);
    }
    CPA_COMMIT(); CPA_WAIT0();
    __syncthreads();

    float qa[2][8][4];
    #pragma unroll
    for (int mf = 0; mf < 2; mf++) {
        const int r0 = m0 + mf * 16 + grp;
        #pragma unroll
        for (int kk = 0; kk < 8; kk++) {
            qa[mf][kk][0] = sm[r0 * STK + kk * 8 + tid4];
            qa[mf][kk][1] = sm[(r0 + 8) * STK + kk * 8 + tid4];
            qa[mf][kk][2] = sm[r0 * STK + kk * 8 + tid4 + 4];
            qa[mf][kk][3] = sm[(r0 + 8) * STK + kk * 8 + tid4 + 4];
        }
    }
    __syncthreads();

    // ---- prologue: chunk 0 -> buffer 0 ----
    #pragma unroll
    for (int i = 0; i < 8; i++) {
        int idx = tid + i * 128;
        CPA16(sb + (((idx >> 4) * STK + (idx & 15) * 4) << 2), kt + idx * 4);
    }
    CPA_COMMIT();

    float l[2][2] = {};
    for (int c = 0; c < NCH; c++) {
        CPA_WAIT0();
        __syncthreads();
        if (c + 1 < NCH) {
            const float* src = kt + (size_t)(c + 1) * KC * DDIM;
            const uint32_t nb = sb + ((c + 1) & 1) * (KC * STK * 4);
            #pragma unroll
            for (int i = 0; i < 8; i++) {
                int idx = tid + i * 128;
                CPA16(nb + (((idx >> 4) * STK + (idx & 15) * 4) << 2), src + idx * 4);
            }
            CPA_COMMIT();
        }
        const float* cur = sm + (c & 1) * (KC * STK);

        #pragma unroll
        for (int fn = 0; fn < 8; fn++) {
            float s[2][4] = {};
            #pragma unroll
            for (int kk = 0; kk < 8; kk++) {
                uint32_t b0 = __float_as_uint(cur[(fn * 8 + grp) * STK + kk * 8 + tid4]);
                uint32_t b1 = __float_as_uint(cur[(fn * 8 + grp) * STK + kk * 8 + tid4 + 4]);
                mma_tf32(s[0], __float_as_uint(qa[0][kk][0]), __float_as_uint(qa[0][kk][1]),
                               __float_as_uint(qa[0][kk][2]), __float_as_uint(qa[0][kk][3]), b0, b1);
                mma_tf32(s[1], __float_as_uint(qa[1][kk][0]), __float_as_uint(qa[1][kk][1]),
                               __float_as_uint(qa[1][kk][2]), __float_as_uint(qa[1][kk][3]), b0, b1);
            }
            #pragma unroll
            for (int mf = 0; mf < 2; mf++) {
                if (mflag) {
                    const float* mr0 = mask + (size_t)(q0 + m0 + mf * 16 + grp) * SSEQ + c * KC + fn * 8 + tid4 * 2;
                    const float* mr1 = mr0 + 8 * SSEQ;
                    float2 v0 = *(const float2*)mr0;
                    float2 v1 = *(const float2*)mr1;
                    s[mf][0] += v0.x; s[mf][1] += v0.y; s[mf][2] += v1.x; s[mf][3] += v1.y;
                }
                l[mf][0] += __expf(s[mf][0]) + __expf(s[mf][1]);
                l[mf][1] += __expf(s[mf][2]) + __expf(s[mf][3]);
            }
        }
    }

    #pragma unroll
    for (int mf = 0; mf < 2; mf++)
        #pragma unroll
        for (int i = 0; i < 2; i++) {
            float x = l[mf][i];
            x += __shfl_xor_sync(0xffffffffu, x, 1);
            x += __shfl_xor_sync(0xffffffffu, x, 2);
            if (tid4 == 0)
                g_li[(size_t)bh * SSEQ + q0 + m0 + mf * 16 + grp + i * 8] = 1.f / x;
        }
}

// ============================================================
// K2: recompute s, p = exp(s)*li -> final weights; PV mma -> O.
// K and V chunks via cp.async double buffer. 128 q-rows/CTA, 4 warps.
// ============================================================
__global__ __launch_bounds__(128, 3)
void pv_w(const float* __restrict__ mask, float* __restrict__ out) {
    extern __shared__ float sm[];
    const int tid = threadIdx.x;
    const int warp = tid >> 5, lane = tid & 31;
    const int grp = lane >> 2, tid4 = lane & 3;
    const int mt = blockIdx.x, bh = blockIdx.y;
    const int q0 = mt * 128;
    const int m0 = warp * 32;
    const size_t base = (size_t)bh * SSEQ * DDIM;
    const int mflag = *(volatile int*)&g_maskFlag;
    const uint32_t sb = smaddr(sm);

    const float* qt = g_qt + base + (size_t)q0 * DDIM;
    const float* kt = g_kt + base;
    const float* vt = g_vt + base;

    const int sl0 = (lane & 28) + (tid4 >> 1);
    const int sl1 = sl0 + 2;
    const bool odd = (tid4 & 1);

    float li[2][2];
    #pragma unroll
    for (int mf = 0; mf < 2; mf++)
        #pragma unroll
        for (int i = 0; i < 2; i++)
            li[mf][i] = g_li[(size_t)bh * SSEQ + q0 + m0 + mf * 16 + grp + i * 8];

    // ---- stage Q over the two K buffers ----
    #pragma unroll
    for (int i = 0; i < 16; i++) {
        int idx = tid + i * 128;
        CPA16(sb + (((idx >> 4) * STK + (idx & 15) * 4) << 2), qt + idx * 4);
    }
    CPA_COMMIT(); CPA_WAIT0();
    __syncthreads();

    float qa[2][8][4];
    #pragma unroll
    for (int mf = 0; mf < 2; mf++) {
        const int r0 = m0 + mf * 16 + grp;
        #pragma unroll
        for (int kk = 0; kk < 8; kk++) {
            qa[mf][kk][0] = sm[r0 * STK + kk * 8 + tid4];
            qa[mf][kk][1] = sm[(r0 + 8) * STK + kk * 8 + tid4];
            qa[mf][kk][2] = sm[r0 * STK + kk * 8 + tid4 + 4];
            qa[mf][kk][3] = sm[(r0 + 8) * STK + kk * 8 + tid4 + 4];
        }
    }
    __syncthreads();

    const uint32_t vbb = sb + 2 * KC * STK * 4;
    // ---- prologue: K0, V0 -> buffers 0 ----
    #pragma unroll
    for (int i = 0; i < 8; i++) {
        int idx = tid + i * 128;
        uint32_t off = ((idx >> 4) * STK + (idx & 15) * 4) << 2;
        CPA16(sb + off, kt + idx * 4);
        uint32_t voff = ((idx >> 4) * STV + (idx & 15) * 4) << 2;
        CPA16(vbb + voff, vt + idx * 4);
    }
    CPA_COMMIT();

    float o[2][8][4] = {};
    float* wb = out + OUT_O_ELEMS + (size_t)bh * SSEQ * SSEQ + (size_t)q0 * SSEQ;

    for (int c = 0; c < NCH; c++) {
        CPA_WAIT0();
        __syncthreads();
        if (c + 1 < NCH) {
            const float* ks = kt + (size_t)(c + 1) * KC * DDIM;
            const float* vs = vt + (size_t)(c + 1) * KC * DDIM;
            const uint32_t kb = sb  + ((c + 1) & 1) * (KC * STK * 4);
            const uint32_t vb = vbb + ((c + 1) & 1) * (KC * STV * 4);
            #pragma unroll
            for (int i = 0; i < 8; i++) {
                int idx = tid + i * 128;
                CPA16(kb + (((idx >> 4) * STK + (idx & 15) * 4) << 2), ks + idx * 4);
                CPA16(vb + (((idx >> 4) * STV + (idx & 15) * 4) << 2), vs + idx * 4);
            }
            CPA_COMMIT();
        }
        const float* kcur = sm + (c & 1) * (KC * STK);
        const float* vcur = sm + 2 * KC * STK + (c & 1) * (KC * STV);

        #pragma unroll
        for (int fn = 0; fn < 8; fn++) {
            float s[2][4] = {};
            #pragma unroll
            for (int kk = 0; kk < 8; kk++) {
                uint32_t b0 = __float_as_uint(kcur[(fn * 8 + grp) * STK + kk * 8 + tid4]);
                uint32_t b1 = __float_as_uint(kcur[(fn * 8 + grp) * STK + kk * 8 + tid4 + 4]);
                mma_tf32(s[0], __float_as_uint(qa[0][kk][0]), __float_as_uint(qa[0][kk][1]),
                               __float_as_uint(qa[0][kk][2]), __float_as_uint(qa[0][kk][3]), b0, b1);
                mma_tf32(s[1], __float_as_uint(qa[1][kk][0]), __float_as_uint(qa[1][kk][1]),
                               __float_as_uint(qa[1][kk][2]), __float_as_uint(qa[1][kk][3]), b0, b1);
            }
            #pragma unroll
            for (int mf = 0; mf < 2; mf++) {
                const int r0 = m0 + mf * 16 + grp;
                if (mflag) {
                    const float* mr0 = mask + (size_t)(q0 + r0) * SSEQ + c * KC + fn * 8 + tid4 * 2;
                    const float* mr1 = mr0 + 8 * SSEQ;
                    float2 v0 = *(const float2*)mr0;
                    float2 v1 = *(const float2*)mr1;
                    s[mf][0] += v0.x; s[mf][1] += v0.y; s[mf][2] += v1.x; s[mf][3] += v1.y;
                }
                float p0 = __expf(s[mf][0]) * li[mf][0];
                float p1 = __expf(s[mf][1]) * li[mf][0];
                float p2 = __expf(s[mf][2]) * li[mf][1];
                float p3 = __expf(s[mf][3]) * li[mf][1];

                float* w0 = wb + (size_t)r0 * SSEQ + c * KC + fn * 8 + tid4 * 2;
                *(float2*)w0 = make_float2(p0, p1);
                *(float2*)(w0 + 8 * SSEQ) = make_float2(p2, p3);

                float x0 = __shfl_sync(0xffffffffu, p0, sl0);
                float x1 = __shfl_sync(0xffffffffu, p1, sl0);
                float x2 = __shfl_sync(0xffffffffu, p2, sl0);
                float x3 = __shfl_sync(0xffffffffu, p3, sl0);
                float y0 = __shfl_sync(0xffffffffu, p0, sl1);
                float y1 = __shfl_sync(0xffffffffu, p1, sl1);
                float y2 = __shfl_sync(0xffffffffu, p2, sl1);
                float y3 = __shfl_sync(0xffffffffu, p3, sl1);
                uint32_t a0 = f2tf32(odd ? x1 : x0);
                uint32_t a1 = f2tf32(odd ? x3 : x2);
                uint32_t a2 = f2tf32(odd ? y1 : y0);
                uint32_t a3 = f2tf32(odd ? y3 : y2);

                #pragma unroll
                for (int nb = 0; nb < 8; nb++) {
                    uint32_t b0 = __float_as_uint(vcur[(fn * 8 + tid4) * STV + nb * 8 + grp]);
                    uint32_t b1 = __float_as_uint(vcur[(fn * 8 + tid4 + 4) * STV + nb * 8 + grp]);
                    mma_tf32(o[mf][nb], a0, a1, a2, a3, b0, b1);
                }
            }
        }
    }

    // ---- write O (already normalized) ----
    float* ob = out + base + (size_t)q0 * DDIM;
    #pragma unroll
    for (int mf = 0; mf < 2; mf++) {
        const int r0 = m0 + mf * 16 + grp;
        #pragma unroll
        for (int nb = 0; nb < 8; nb++) {
            int col = nb * 8 + tid4 * 2;
            *(float2*)&ob[(size_t)r0 * DDIM + col]       = make_float2(o[mf][nb][0], o[mf][nb][1]);
            *(float2*)&ob[(size_t)(r0 + 8) * DDIM + col] = make_float2(o[mf][nb][2], o[mf][nb][3]);
        }
    }
}

extern "C" void kernel_launch(void* const* d_in, const int* in_sizes, int n_in,
                              void* d_out, int out_size) {
    const float* q    = (const float*)d_in[0];
    const float* k    = (const float*)d_in[1];
    const float* v    = (const float*)d_in[2];
    const float* mask = (const float*)d_in[3];
    float* out = (float*)d_out;

    cudaFuncSetAttribute(qk_li, cudaFuncAttributeMaxDynamicSharedMemorySize, SM1_BYTES);
    cudaFuncSetAttribute(pv_w,  cudaFuncAttributeMaxDynamicSharedMemorySize, SM2_BYTES);

    mask_check<<<2048, 256>>>(mask, (size_t)SSEQ * SSEQ);
    prep<<<2048, 256>>>(q, k, v);
    qk_li<<<dim3(16, BB * HH), 128, SM1_BYTES>>>(mask);
    pv_w<<<dim3(16, BB * HH), 128, SM2_BYTES>>>(mask, out);
}